// round 8
// baseline (speedup 1.0000x reference)
#include <cuda_runtime.h>
#include <cstdint>
#include <cstddef>

#define N_NODES 50000
#define N_EDGES 800000
#define NB_SCAN 196          // ceil(50000/256)

// Scratch (device globals: no runtime allocation allowed)
__device__ __align__(16) float g_xw1[N_NODES * 64];   // x@W1[:64]+b1
__device__ __align__(16) float g_agg[N_NODES * 64];   // per-node sum of relu(h)
__device__ __align__(16) float g_pef[(size_t)N_EDGES * 16];  // ef sorted by dst (51.2 MB)
__device__ __align__(16) float g_wc[64 * 64];         // W2 @ W3[64:128,:]
__device__ float g_bc[64];                            // b2 @ W3[64:128,:]
__device__ int g_cnt[N_NODES];
__device__ int g_base[N_NODES];
__device__ int g_cursor[N_NODES];
__device__ int g_psrc[N_EDGES];                       // src, dst-sorted
__device__ int g_pdst[N_EDGES];                       // dst, dst-sorted
__device__ int g_bsum[NB_SCAN];
__device__ int g_boff[256];

typedef unsigned long long u64;

__device__ __forceinline__ u64 pack2(float v) {
    u64 r; asm("mov.b64 %0, {%1, %1};" : "=l"(r) : "f"(v)); return r;
}
__device__ __forceinline__ u64 pack2f(float lo, float hi) {
    u64 r; asm("mov.b64 %0, {%1, %2};" : "=l"(r) : "f"(lo), "f"(hi)); return r;
}
__device__ __forceinline__ void unpack2(u64 v, float &lo, float &hi) {
    asm("mov.b64 {%0, %1}, %2;" : "=f"(lo), "=f"(hi) : "l"(v));
}
__device__ __forceinline__ void ffma2(u64 &d, u64 a, u64 b) {
    asm("fma.rn.f32x2 %0, %1, %2, %0;" : "+l"(d) : "l"(a), "l"(b));
}
__device__ __forceinline__ void red_add_v2(float* addr, float vx, float vy) {
    asm volatile("red.global.add.v2.f32 [%0], {%1, %2};"
                 :: "l"(addr), "f"(vx), "f"(vy) : "memory");
}

// ---------------------------------------------------------------------------
// K0: Wc = W2 @ W3[64:128,:],  bc = b2 @ W3[64:128,:]
// ---------------------------------------------------------------------------
__global__ void __launch_bounds__(64) prep_kernel(
        const float* __restrict__ W2,
        const float* __restrict__ W3,
        const float* __restrict__ b2) {
    __shared__ float sw2[64];
    int i = blockIdx.x, j = threadIdx.x;
    sw2[j] = W2[i * 64 + j];
    __syncthreads();
    float acc = 0.0f;
    #pragma unroll 8
    for (int k = 0; k < 64; k++)
        acc = fmaf(sw2[k], W3[(64 + k) * 64 + j], acc);
    g_wc[i * 64 + j] = acc;
    if (i == 0) {
        float accb = 0.0f;
        for (int k = 0; k < 64; k++)
            accb = fmaf(b2[k], W3[(64 + k) * 64 + j], accb);
        g_bc[j] = accb;
    }
}

// ---------------------------------------------------------------------------
// K1: g_xw1[n] = x[n] @ W1[0:64,:] + b1 ; zero g_agg row, g_cnt.
// M=2 node blocking: thread handles n0 and n1=n0+128 (weights LDS shared).
// ---------------------------------------------------------------------------
__global__ void __launch_bounds__(128) precompute_kernel(
        const float* __restrict__ x,
        const float* __restrict__ W1,
        const float* __restrict__ b1) {
    __shared__ ulonglong2 sW[64 * 16];   // 16 KB
    __shared__ ulonglong2 sb[16];
    int tid = threadIdx.x;
    const ulonglong2* W1v = reinterpret_cast<const ulonglong2*>(W1);
    for (int idx = tid; idx < 64 * 16; idx += 128) sW[idx] = W1v[idx];
    if (tid < 16) sb[tid] = reinterpret_cast<const ulonglong2*>(b1)[tid];
    __syncthreads();

    int n0 = blockIdx.x * 256 + tid;
    int n1 = n0 + 128;
    bool vA = (n0 < N_NODES), vB = (n1 < N_NODES);
    int nA = vA ? n0 : 0, nB = vB ? n1 : 0;

    u64 accA[32], accB[32];
    #pragma unroll
    for (int j = 0; j < 16; j++) {
        ulonglong2 v = sb[j];
        accA[2*j] = v.x; accA[2*j+1] = v.y;
        accB[2*j] = v.x; accB[2*j+1] = v.y;
    }

    const float4* xA = reinterpret_cast<const float4*>(x + (size_t)nA * 64);
    const float4* xB = reinterpret_cast<const float4*>(x + (size_t)nB * 64);

    #pragma unroll 1
    for (int c = 0; c < 4; c++) {
        float va[16], vb[16];
        #pragma unroll
        for (int j = 0; j < 4; j++) {
            float4 fa = xA[c * 4 + j];
            float4 fb = xB[c * 4 + j];
            va[4*j] = fa.x; va[4*j+1] = fa.y; va[4*j+2] = fa.z; va[4*j+3] = fa.w;
            vb[4*j] = fb.x; vb[4*j+1] = fb.y; vb[4*j+2] = fb.z; vb[4*j+3] = fb.w;
        }
        #pragma unroll
        for (int i = 0; i < 16; i++) {
            u64 a0 = pack2(va[i]);
            u64 a1 = pack2(vb[i]);
            #pragma unroll
            for (int j = 0; j < 16; j++) {
                ulonglong2 w = sW[(c * 16 + i) * 16 + j];
                ffma2(accA[2*j], a0, w.x); ffma2(accA[2*j+1], a0, w.y);
                ffma2(accB[2*j], a1, w.x); ffma2(accB[2*j+1], a1, w.y);
            }
        }
    }
    float4 z = make_float4(0.f, 0.f, 0.f, 0.f);
    if (vA) {
        ulonglong2* o = reinterpret_cast<ulonglong2*>(g_xw1 + (size_t)n0 * 64);
        float4* az = reinterpret_cast<float4*>(g_agg + (size_t)n0 * 64);
        #pragma unroll
        for (int j = 0; j < 16; j++) {
            ulonglong2 v; v.x = accA[2*j]; v.y = accA[2*j+1]; o[j] = v;
            az[j] = z;
        }
        g_cnt[n0] = 0;
    }
    if (vB) {
        ulonglong2* o = reinterpret_cast<ulonglong2*>(g_xw1 + (size_t)n1 * 64);
        float4* az = reinterpret_cast<float4*>(g_agg + (size_t)n1 * 64);
        #pragma unroll
        for (int j = 0; j < 16; j++) {
            ulonglong2 v; v.x = accB[2*j]; v.y = accB[2*j+1]; o[j] = v;
            az[j] = z;
        }
        g_cnt[n1] = 0;
    }
}

// ---------------------------------------------------------------------------
// K2: count in-degrees
// ---------------------------------------------------------------------------
__global__ void __launch_bounds__(256) count_kernel(const int* __restrict__ ei) {
    int e = blockIdx.x * 256 + threadIdx.x;
    atomicAdd(&g_cnt[ei[N_EDGES + e]], 1);
}

// ---------------------------------------------------------------------------
// K3a/b/c: two-level parallel exclusive scan of g_cnt -> g_base, g_cursor
// ---------------------------------------------------------------------------
__global__ void __launch_bounds__(256) scanA_kernel() {
    int b = blockIdx.x, tid = threadIdx.x;
    int idx = b * 256 + tid;
    int v = (idx < N_NODES) ? g_cnt[idx] : 0;
    __shared__ int ws[8];
    #pragma unroll
    for (int o = 16; o > 0; o >>= 1) v += __shfl_down_sync(0xffffffffu, v, o);
    if ((tid & 31) == 0) ws[tid >> 5] = v;
    __syncthreads();
    if (tid == 0) {
        int s = 0;
        #pragma unroll
        for (int k = 0; k < 8; k++) s += ws[k];
        g_bsum[b] = s;
    }
}

__global__ void __launch_bounds__(256) scanB_kernel() {
    int tid = threadIdx.x, lane = tid & 31, w = tid >> 5;
    int v = (tid < NB_SCAN) ? g_bsum[tid] : 0;
    int inc = v;
    __shared__ int ws[8];
    #pragma unroll
    for (int o = 1; o < 32; o <<= 1) {
        int t = __shfl_up_sync(0xffffffffu, inc, o);
        if (lane >= o) inc += t;
    }
    if (lane == 31) ws[w] = inc;
    __syncthreads();
    int off = 0;
    #pragma unroll
    for (int k = 0; k < 8; k++) off += (k < w) ? ws[k] : 0;
    g_boff[tid] = off + inc - v;   // exclusive
}

__global__ void __launch_bounds__(256) scanC_kernel() {
    int b = blockIdx.x, tid = threadIdx.x, lane = tid & 31, w = tid >> 5;
    int idx = b * 256 + tid;
    int c = (idx < N_NODES) ? g_cnt[idx] : 0;
    int inc = c;
    __shared__ int ws[8];
    #pragma unroll
    for (int o = 1; o < 32; o <<= 1) {
        int t = __shfl_up_sync(0xffffffffu, inc, o);
        if (lane >= o) inc += t;
    }
    if (lane == 31) ws[w] = inc;
    __syncthreads();
    int off = g_boff[b];
    #pragma unroll
    for (int k = 0; k < 8; k++) off += (k < w) ? ws[k] : 0;
    int base = off + inc - c;
    if (idx < N_NODES) { g_base[idx] = base; g_cursor[idx] = base; }
}

// ---------------------------------------------------------------------------
// K4: place edges into dst-sorted buckets; carry src, dst AND edge features
// (ef read coalesced here; scattered stores are latency-tolerant).
// ---------------------------------------------------------------------------
__global__ void __launch_bounds__(256) place_kernel(
        const int* __restrict__ ei,
        const float* __restrict__ ef) {
    int e = blockIdx.x * 256 + threadIdx.x;
    int d = ei[N_EDGES + e];
    int pos = atomicAdd(&g_cursor[d], 1);
    g_psrc[pos] = ei[e];
    g_pdst[pos] = d;
    const float4* er = reinterpret_cast<const float4*>(ef + (size_t)e * 16);
    float4* o = reinterpret_cast<float4*>(g_pef + (size_t)pos * 16);
    float4 f0 = er[0], f1 = er[1], f2 = er[2], f3 = er[3];
    o[0] = f0; o[1] = f1; o[2] = f2; o[3] = f3;
}

// ---------------------------------------------------------------------------
// K5: aggregate over sorted slots. Block = 128 slots.
//   m = relu(xw1[src] + pef@W1e)  -> smem
//   segment (equal-dst run) reduce -> red.add.v2 into g_agg
// ---------------------------------------------------------------------------
__global__ void __launch_bounds__(128) aggregate_kernel(
        const float* __restrict__ W1) {
    __shared__ ulonglong2 sW1e[16 * 16];          // 4 KB
    __shared__ float sm[128 * 66];                // 33 KB, stride 66
    __shared__ int sdst[128];
    __shared__ int sheads[129];
    __shared__ int snseg;

    int tid = threadIdx.x;
    sW1e[tid * 2]     = reinterpret_cast<const ulonglong2*>(W1)[1024 + tid * 2];
    sW1e[tid * 2 + 1] = reinterpret_cast<const ulonglong2*>(W1)[1024 + tid * 2 + 1];
    if (tid == 0) snseg = 0;

    int slot = blockIdx.x * 128 + tid;            // N_EDGES % 128 == 0
    int src = g_psrc[slot];
    int d   = g_pdst[slot];
    sdst[tid] = d;

    // message compute
    u64 acc[32];
    const ulonglong2* xr = reinterpret_cast<const ulonglong2*>(g_xw1 + (size_t)src * 64);
    #pragma unroll
    for (int j = 0; j < 16; j++) { ulonglong2 v = xr[j]; acc[2*j] = v.x; acc[2*j+1] = v.y; }

    float efr[16];
    const float4* er = reinterpret_cast<const float4*>(g_pef + (size_t)slot * 16);
    #pragma unroll
    for (int j = 0; j < 4; j++) {
        float4 f = er[j];
        efr[4*j] = f.x; efr[4*j+1] = f.y; efr[4*j+2] = f.z; efr[4*j+3] = f.w;
    }
    __syncthreads();   // sW1e/sdst/snseg ready

    #pragma unroll
    for (int i = 0; i < 16; i++) {
        u64 a = pack2(efr[i]);
        #pragma unroll
        for (int j = 0; j < 16; j++) {
            ulonglong2 w = sW1e[i * 16 + j];
            ffma2(acc[2*j], a, w.x);
            ffma2(acc[2*j+1], a, w.y);
        }
    }

    // relu -> smem
    float2* myrow = reinterpret_cast<float2*>(sm + tid * 66);
    #pragma unroll
    for (int j = 0; j < 32; j++) {
        float lo, hi; unpack2(acc[j], lo, hi);
        myrow[j] = make_float2(fmaxf(lo, 0.f), fmaxf(hi, 0.f));
    }

    bool ishead = (tid == 0) || (sdst[tid - 1] != d);
    __syncthreads();
    if (ishead) {
        int i = atomicAdd(&snseg, 1);
        sheads[i] = tid;
    }
    __syncthreads();

    int nseg = snseg;
    int warp = tid >> 5, lane = tid & 31;
    for (int sidx = warp; sidx < nseg; sidx += 4) {
        int a = sheads[sidx];
        int d0 = sdst[a];
        int b = a + 1;
        while (b < 128) {
            int t = b + lane;
            bool diff = (t >= 128) || (sdst[t] != d0);
            unsigned m = __ballot_sync(0xffffffffu, diff);
            if (m) { b += __ffs(m) - 1; break; }
            b += 32;
        }
        float sx = 0.f, sy = 0.f;
        for (int t = a; t < b; t++) {
            float2 v = *reinterpret_cast<const float2*>(sm + t * 66 + 2 * lane);
            sx += v.x; sy += v.y;
        }
        red_add_v2(g_agg + (size_t)d0 * 64 + 2 * lane, sx, sy);
    }
}

// ---------------------------------------------------------------------------
// K6: fused update+LN (nodeA folded via Wc/bc), M=2 node blocking:
//   acc = x@W3[0:64] + (aggsum*inv)@Wc + b3 + bc*(cnt*inv)
//   y = relu(acc) + x ; LayerNorm -> out
// ---------------------------------------------------------------------------
__global__ void __launch_bounds__(128) nodeB_kernel(
        const float* __restrict__ x,
        const float* __restrict__ W3,
        const float* __restrict__ b3,
        const float* __restrict__ gamma,
        const float* __restrict__ beta,
        float* __restrict__ out) {
    __shared__ ulonglong2 sW[128 * 16];  // 32 KB: rows 0..63 W3 top, 64..127 Wc
    __shared__ float sb3[64], sbc[64], sg[64], sbt[64];
    int tid = threadIdx.x;
    const ulonglong2* W3v = reinterpret_cast<const ulonglong2*>(W3);
    const ulonglong2* Wcv = reinterpret_cast<const ulonglong2*>(g_wc);
    for (int idx = tid; idx < 64 * 16; idx += 128) {
        sW[idx] = W3v[idx];
        sW[64 * 16 + idx] = Wcv[idx];
    }
    if (tid < 64) { sb3[tid] = b3[tid]; sbc[tid] = g_bc[tid]; sg[tid] = gamma[tid]; sbt[tid] = beta[tid]; }
    __syncthreads();

    int n0 = blockIdx.x * 256 + tid;
    int n1 = n0 + 128;
    bool vA = (n0 < N_NODES), vB = (n1 < N_NODES);
    int nA = vA ? n0 : 0, nB = vB ? n1 : 0;

    float cntA = (float)g_cnt[nA];
    float cntB = (float)g_cnt[nB];
    float invA = 1.0f / (cntA + 1e-8f), invB = 1.0f / (cntB + 1e-8f);
    float bsA = cntA * invA, bsB = cntB * invB;

    u64 accA[32], accB[32];
    #pragma unroll
    for (int j = 0; j < 32; j++) {
        accA[j] = pack2f(fmaf(bsA, sbc[2*j], sb3[2*j]), fmaf(bsA, sbc[2*j+1], sb3[2*j+1]));
        accB[j] = pack2f(fmaf(bsB, sbc[2*j], sb3[2*j]), fmaf(bsB, sbc[2*j+1], sb3[2*j+1]));
    }

    const float4* xA = reinterpret_cast<const float4*>(x + (size_t)nA * 64);
    const float4* xB = reinterpret_cast<const float4*>(x + (size_t)nB * 64);
    const float4* aA = reinterpret_cast<const float4*>(g_agg + (size_t)nA * 64);
    const float4* aB = reinterpret_cast<const float4*>(g_agg + (size_t)nB * 64);

    #pragma unroll 1
    for (int c = 0; c < 8; c++) {
        bool isx = (c < 4);
        const float4* pA = isx ? (xA + c * 4) : (aA + (c - 4) * 4);
        const float4* pB = isx ? (xB + c * 4) : (aB + (c - 4) * 4);
        float va[16], vb[16];
        #pragma unroll
        for (int j = 0; j < 4; j++) {
            float4 fa = pA[j];
            float4 fb = pB[j];
            va[4*j] = fa.x; va[4*j+1] = fa.y; va[4*j+2] = fa.z; va[4*j+3] = fa.w;
            vb[4*j] = fb.x; vb[4*j+1] = fb.y; vb[4*j+2] = fb.z; vb[4*j+3] = fb.w;
        }
        if (!isx) {
            #pragma unroll
            for (int j = 0; j < 16; j++) { va[j] *= invA; vb[j] *= invB; }
        }
        #pragma unroll
        for (int i = 0; i < 16; i++) {
            u64 a0 = pack2(va[i]);
            u64 a1 = pack2(vb[i]);
            #pragma unroll
            for (int j = 0; j < 16; j++) {
                ulonglong2 w = sW[(c * 16 + i) * 16 + j];
                ffma2(accA[2*j], a0, w.x); ffma2(accA[2*j+1], a0, w.y);
                ffma2(accB[2*j], a1, w.x); ffma2(accB[2*j+1], a1, w.y);
            }
        }
    }

    // finalize node A then node B (reuse registers)
    #pragma unroll 1
    for (int m = 0; m < 2; m++) {
        bool valid = m ? vB : vA;
        if (!valid) continue;
        int n = m ? n1 : n0;
        u64* acc = m ? accB : accA;
        const float4* xr = reinterpret_cast<const float4*>(x + (size_t)n * 64);

        float u[64];
        #pragma unroll
        for (int j = 0; j < 16; j++) {
            float4 f = xr[j];
            float a0, a1, a2, a3;
            unpack2(acc[2*j],   a0, a1);
            unpack2(acc[2*j+1], a2, a3);
            u[4*j]   = fmaxf(a0, 0.0f) + f.x;
            u[4*j+1] = fmaxf(a1, 0.0f) + f.y;
            u[4*j+2] = fmaxf(a2, 0.0f) + f.z;
            u[4*j+3] = fmaxf(a3, 0.0f) + f.w;
        }
        float s = 0.0f, ss = 0.0f;
        #pragma unroll
        for (int j = 0; j < 64; j++) { s += u[j]; ss = fmaf(u[j], u[j], ss); }
        float mu  = s * (1.0f / 64.0f);
        float var = ss * (1.0f / 64.0f) - mu * mu;
        float r   = rsqrtf(var + 1e-5f);

        float4* o = reinterpret_cast<float4*>(out + (size_t)n * 64);
        #pragma unroll
        for (int j = 0; j < 16; j++) {
            float4 v;
            v.x = (u[4*j]   - mu) * r * sg[4*j]   + sbt[4*j];
            v.y = (u[4*j+1] - mu) * r * sg[4*j+1] + sbt[4*j+1];
            v.z = (u[4*j+2] - mu) * r * sg[4*j+2] + sbt[4*j+2];
            v.w = (u[4*j+3] - mu) * r * sg[4*j+3] + sbt[4*j+3];
            o[j] = v;
        }
    }
}

// ---------------------------------------------------------------------------
extern "C" void kernel_launch(void* const* d_in, const int* in_sizes, int n_in,
                              void* d_out, int out_size) {
    const float* x     = (const float*)d_in[0];
    const int*   ei    = (const int*)  d_in[1];
    const float* ef    = (const float*)d_in[2];
    const float* W1    = (const float*)d_in[3];
    const float* b1    = (const float*)d_in[4];
    const float* W2    = (const float*)d_in[5];
    const float* b2    = (const float*)d_in[6];
    const float* W3    = (const float*)d_in[7];
    const float* b3    = (const float*)d_in[8];
    const float* gamma = (const float*)d_in[9];
    const float* beta  = (const float*)d_in[10];
    float* out = (float*)d_out;

    (void)in_sizes; (void)n_in; (void)out_size;

    const int nb256 = (N_NODES + 255) / 256;

    prep_kernel<<<64, 64>>>(W2, W3, b2);
    precompute_kernel<<<nb256, 128>>>(x, W1, b1);
    count_kernel<<<N_EDGES / 256, 256>>>(ei);
    scanA_kernel<<<NB_SCAN, 256>>>();
    scanB_kernel<<<1, 256>>>();
    scanC_kernel<<<NB_SCAN, 256>>>();
    place_kernel<<<N_EDGES / 256, 256>>>(ei, ef);
    aggregate_kernel<<<N_EDGES / 128, 128>>>(W1);
    nodeB_kernel<<<nb256, 128>>>(x, W3, b3, gamma, beta, out);
}